// round 12
// baseline (speedup 1.0000x reference)
#include <cuda_runtime.h>
#include <cuda_bf16.h>
#include <math.h>
#include <stdint.h>
#include <string.h>

#define BB 2
#define SS 2048
#define DD 1024
#define HH 16
#define DK 64
#define MM (BB*SS)   // 4096
#define PLSTR (BB*HH*SS*32)   // words per bf16 plane (2,097,152)

// ---------------- scratch (static device memory; no allocations) ----------------
__device__ uint32_t g_Qbf[2*PLSTR];  // [pl][bh][s][32w] bf16x2, rope'd, x0.125
__device__ uint32_t g_Kbf[2*PLSTR];  // [pl][bh][s][32w] bf16x2, rope'd
__device__ uint32_t g_Vbf[2*PLSTR];  // [pl][bh][s][32w] bf16x2
__device__ float    g_attn[BB*SS*DD];

// ---------------- TF32 helpers (GEMMs) ----------------
__device__ __forceinline__ float to_tf32(float x) {
    float y;
    asm("cvt.rna.tf32.f32 %0, %1;" : "=f"(y) : "f"(x));
    return y;
}

__device__ __forceinline__ void mma_tf32(float c[4],
                                         uint32_t a0, uint32_t a1, uint32_t a2, uint32_t a3,
                                         uint32_t b0, uint32_t b1)
{
    asm volatile("mma.sync.aligned.m16n8k8.row.col.f32.tf32.tf32.f32 "
                 "{%0,%1,%2,%3}, {%4,%5,%6,%7}, {%8,%9}, {%0,%1,%2,%3};"
                 : "+f"(c[0]), "+f"(c[1]), "+f"(c[2]), "+f"(c[3])
                 : "r"(a0), "r"(a1), "r"(a2), "r"(a3), "r"(b0), "r"(b1));
}

// ---------------- BF16 helpers (attention) ----------------
__device__ __forceinline__ void mma_bf16(float c[4],
                                         uint32_t a0, uint32_t a1, uint32_t a2, uint32_t a3,
                                         uint32_t b0, uint32_t b1)
{
    asm volatile("mma.sync.aligned.m16n8k16.row.col.f32.bf16.bf16.f32 "
                 "{%0,%1,%2,%3}, {%4,%5,%6,%7}, {%8,%9}, {%0,%1,%2,%3};"
                 : "+f"(c[0]), "+f"(c[1]), "+f"(c[2]), "+f"(c[3])
                 : "r"(a0), "r"(a1), "r"(a2), "r"(a3), "r"(b0), "r"(b1));
}

__device__ __forceinline__ void ldsm_x4(uint32_t& r0, uint32_t& r1,
                                        uint32_t& r2, uint32_t& r3, uint32_t addr)
{
    asm volatile("ldmatrix.sync.aligned.m8n8.x4.shared.b16 {%0,%1,%2,%3}, [%4];"
                 : "=r"(r0), "=r"(r1), "=r"(r2), "=r"(r3) : "r"(addr));
}

__device__ __forceinline__ void ldsm_x4_t(uint32_t& r0, uint32_t& r1,
                                          uint32_t& r2, uint32_t& r3, uint32_t addr)
{
    asm volatile("ldmatrix.sync.aligned.m8n8.x4.trans.shared.b16 {%0,%1,%2,%3}, [%4];"
                 : "=r"(r0), "=r"(r1), "=r"(r2), "=r"(r3) : "r"(addr));
}

__device__ __forceinline__ void cp_async16(uint32_t saddr, const void* gptr) {
    asm volatile("cp.async.cg.shared.global [%0], [%1], 16;"
                 :: "r"(saddr), "l"(gptr));
}
__device__ __forceinline__ void cp_commit() {
    asm volatile("cp.async.commit_group;");
}
template<int N>
__device__ __forceinline__ void cp_wait() {
    asm volatile("cp.async.wait_group %0;" :: "n"(N));
}

// hi = bf16x2(x,y), lo = bf16x2(x-hi.x, y-hi.y)
__device__ __forceinline__ void split_bf16(float x, float y, uint32_t& hi, uint32_t& lo)
{
    __nv_bfloat162 h = __floats2bfloat162_rn(x, y);
    float hx = __bfloat162float(h.x);
    float hy = __bfloat162float(h.y);
    __nv_bfloat162 l = __floats2bfloat162_rn(x - hx, y - hy);
    hi = *reinterpret_cast<uint32_t*>(&h);
    lo = *reinterpret_cast<uint32_t*>(&l);
}

// ---------------- TF32 GEMM: C = A[4096,1024] @ W[1024,1024] ----------------
// cp.async double-buffered pipeline, K-tile 32, fp32 in smem, cvt at frag load.
// mode 0: plain fp32 write; 1: RoPE+scale+split planes (Q); 2: RoPE+split (K);
// 3: split (V).
#define ASTR 36    // 32 k + 4 pad  (bank = 4g+t distinct)
#define BSTR 136   // 128 n + 8 pad (bank = 8t+g distinct)
#define GA_BUF (128*ASTR)            // 4608 floats per A buffer
#define GB_BUF (32*BSTR)             // 4352 floats per B buffer
#define GB_BASE (2*GA_BUF)           // 9216
#define GEMM_SMEM_FLOATS (2*GA_BUF + 2*GB_BUF)   // 17920 floats = 71680 B

__global__ void __launch_bounds__(256, 2)
gemm_tf32_kernel(const float* __restrict__ A, const float* __restrict__ W,
                 void* __restrict__ Cout, int mode,
                 const int* __restrict__ tpos,
                 const float* __restrict__ cosT,
                 const float* __restrict__ sinT)
{
    const int K = 1024, N = 1024;
    extern __shared__ float gsm[];

    const int tid  = threadIdx.x;
    const int warp = tid >> 5;
    const int lane = tid & 31;
    const int g = lane >> 2;
    const int t = lane & 3;

    const int wm = warp & 1;
    const int wn = warp >> 1;
    const int warp_m = wm * 64;
    const int warp_n = wn * 32;

    const int row0 = blockIdx.y * 128;
    const int col0 = blockIdx.x * 128;

    // staging assignments (16 floats = 4x16B per thread per tensor per tile)
    const int a_row = tid >> 1;          // 0..127
    const int a_c0  = (tid & 1) * 16;    // 0 or 16
    const int b_row = tid >> 3;          // 0..31
    const int b_c0  = (tid & 7) * 16;    // 0..112

    const uint32_t smb = (uint32_t)__cvta_generic_to_shared(gsm);
    const float* Ap = &A[(long)(row0 + a_row) * K + a_c0];
    const float* Wp = &W[(long)b_row * N + col0 + b_c0];

    float acc[4][4][4];
    #pragma unroll
    for (int i = 0; i < 4; i++)
        #pragma unroll
        for (int j = 0; j < 4; j++)
            #pragma unroll
            for (int r = 0; r < 4; r++)
                acc[i][j][r] = 0.0f;

    // ---- issue tile 0 into buffer 0 ----
    {
        const uint32_t adst = smb + ((a_row * ASTR + a_c0) << 2);
        #pragma unroll
        for (int j = 0; j < 4; j++)
            cp_async16(adst + j * 16, Ap + j * 4);
        const uint32_t bdst = smb + ((GB_BASE + b_row * BSTR + b_c0) << 2);
        #pragma unroll
        for (int j = 0; j < 4; j++)
            cp_async16(bdst + j * 16, Wp + j * 4);
        cp_commit();
    }

    for (int k0 = 0; k0 < K; k0 += 32) {
        const int buf = (k0 >> 5) & 1;

        cp_wait<0>();
        __syncthreads();   // tile k0 visible; previous buffer's readers done

        // ---- issue tile k0+32 into the other buffer ----
        if (k0 + 32 < K) {
            const uint32_t adst = smb + (((1 - buf) * GA_BUF + a_row * ASTR + a_c0) << 2);
            #pragma unroll
            for (int j = 0; j < 4; j++)
                cp_async16(adst + j * 16, Ap + k0 + 32 + j * 4);
            const uint32_t bdst = smb + ((GB_BASE + (1 - buf) * GB_BUF + b_row * BSTR + b_c0) << 2);
            #pragma unroll
            for (int j = 0; j < 4; j++)
                cp_async16(bdst + j * 16, Wp + (long)(k0 + 32) * N + j * 4);
            cp_commit();
        }

        const float* Af = gsm + buf * GA_BUF;
        const float* Bf = gsm + GB_BASE + buf * GB_BUF;

        // ---- compute tile k0 (4 chunks of k8; cvt at frag load) ----
        #pragma unroll
        for (int chunk = 0; chunk < 4; chunk++) {
            const int kc = chunk * 8;

            uint32_t af[4][4];
            #pragma unroll
            for (int fm = 0; fm < 4; fm++) {
                const float* pa = &Af[(warp_m + fm * 16 + g) * ASTR + kc + t];
                af[fm][0] = __float_as_uint(to_tf32(pa[0]));
                af[fm][1] = __float_as_uint(to_tf32(pa[8 * ASTR]));
                af[fm][2] = __float_as_uint(to_tf32(pa[4]));
                af[fm][3] = __float_as_uint(to_tf32(pa[8 * ASTR + 4]));
            }
            uint32_t bf[4][2];
            #pragma unroll
            for (int fn = 0; fn < 4; fn++) {
                const float* pb = &Bf[(kc + t) * BSTR + warp_n + fn * 8 + g];
                bf[fn][0] = __float_as_uint(to_tf32(pb[0]));
                bf[fn][1] = __float_as_uint(to_tf32(pb[4 * BSTR]));
            }

            #pragma unroll
            for (int fm = 0; fm < 4; fm++)
                #pragma unroll
                for (int fn = 0; fn < 4; fn++)
                    mma_tf32(acc[fm][fn],
                             af[fm][0], af[fm][1], af[fm][2], af[fm][3],
                             bf[fn][0], bf[fn][1]);
        }
    }

    if (mode == 0) {
        float* C = (float*)Cout;
        #pragma unroll
        for (int fm = 0; fm < 4; fm++) {
            #pragma unroll
            for (int fn = 0; fn < 4; fn++) {
                int r0 = row0 + warp_m + fm * 16 + g;
                int c0 = col0 + warp_n + fn * 8 + 2 * t;
                *(float2*)&C[(long)r0 * N + c0] =
                    make_float2(acc[fm][fn][0], acc[fm][fn][1]);
                *(float2*)&C[(long)(r0 + 8) * N + c0] =
                    make_float2(acc[fm][fn][2], acc[fm][fn][3]);
            }
        }
    } else {
        uint32_t* Cb = (uint32_t*)Cout;
        #pragma unroll
        for (int fm = 0; fm < 4; fm++) {
            const int m0r = row0 + warp_m + fm * 16 + g;   // token index
            const int bb = m0r >> 11;
            const int s0 = m0r & 2047;
            const int s1 = s0 + 8;
            int p0 = 0, p1 = 0;
            if (mode != 3) { p0 = tpos[s0]; p1 = tpos[s1]; }
            #pragma unroll
            for (int fn = 0; fn < 4; fn++) {
                const int c0 = col0 + warp_n + fn * 8 + 2 * t;
                const int hh = c0 >> 6;
                const int d  = c0 & 63;
                const int pi = d >> 1;
                float x0 = acc[fm][fn][0], y0 = acc[fm][fn][1];
                float x1 = acc[fm][fn][2], y1 = acc[fm][fn][3];
                if (mode != 3) {
                    float cc = cosT[p0 * 32 + pi], ssn = sinT[p0 * 32 + pi];
                    float xe = cc * x0 - ssn * y0;
                    float xo = ssn * x0 + cc * y0;
                    x0 = xe; y0 = xo;
                    cc = cosT[p1 * 32 + pi]; ssn = sinT[p1 * 32 + pi];
                    xe = cc * x1 - ssn * y1;
                    xo = ssn * x1 + cc * y1;
                    x1 = xe; y1 = xo;
                }
                if (mode == 1) {
                    x0 *= 0.125f; y0 *= 0.125f;
                    x1 *= 0.125f; y1 *= 0.125f;
                }
                uint32_t hi0, lo0, hi1, lo1;
                split_bf16(x0, y0, hi0, lo0);
                split_bf16(x1, y1, hi1, lo1);
                const long i0 = ((long)(bb * HH + hh) * SS + s0) * 32 + pi;
                const long i1 = ((long)(bb * HH + hh) * SS + s1) * 32 + pi;
                Cb[i0]         = hi0;
                Cb[PLSTR + i0] = lo0;
                Cb[i1]         = hi1;
                Cb[PLSTR + i1] = lo1;
            }
        }
    }
}

// ---------------- flash attention (unchanged from R10) ----------------
__global__ void __launch_bounds__(128, 4)
flash_attn_kernel()
{
    __shared__ uint32_t smw[12288];   // 48 KB

    const int tid  = threadIdx.x;
    const int warp = tid >> 5;
    const int lane = tid & 31;
    const int g = lane >> 2;
    const int t = lane & 3;

    const int bx = gridDim.x - 1 - blockIdx.x;   // heavy tiles first
    const int bh = blockIdx.y;
    const int b = bh >> 4, h = bh & 15;
    const long hb32 = (long)bh * SS * 32;
    const int q0 = bx * 64;

    const uint32_t smb = (uint32_t)__cvta_generic_to_shared(smw);

    const int sr = tid >> 2;
    const int sc = tid & 3;
    const int qr = tid >> 1;
    const int qc = (tid & 1) * 4;

    // ---- issue Q + tile 0 (buf 0) cp.async ----
    {
        #pragma unroll
        for (int pl = 0; pl < 2; pl++)
            #pragma unroll
            for (int j = 0; j < 4; j++) {
                const int cc = qc + j;
                cp_async16(smb + ((pl * 2048 + (qr << 5) + ((cc ^ (qr & 7)) << 2)) << 2),
                           g_Qbf + (long)pl * PLSTR + hb32 + (long)(q0 + qr) * 32 + cc * 4);
            }
        #pragma unroll
        for (int pl = 0; pl < 2; pl++)
            #pragma unroll
            for (int j = 0; j < 2; j++) {
                const int cc = sc + j * 4;
                const uint32_t koff = (sr << 5) + ((cc ^ (sr & 7)) << 2);
                cp_async16(smb + ((4096 + pl * 1024 + koff) << 2),
                           g_Kbf + (long)pl * PLSTR + hb32 + (long)sr * 32 + cc * 4);
                cp_async16(smb + ((4096 + 2048 + pl * 1024 + koff) << 2),
                           g_Vbf + (long)pl * PLSTR + hb32 + (long)sr * 32 + cc * 4);
            }
        cp_commit();
    }

    const int lr  = lane & 7;
    const int sel = lane >> 3;
    const uint32_t qab = smb + (uint32_t)(warp * 16 + lr + 8 * (sel & 1)) * 128;
    const int aAc = sel >> 1;
    const uint32_t kab_l = smb + (uint32_t)lane * 128;
    const int vfo = lr;

    float m0 = -1e30f, m1 = -1e30f, l0 = 0.0f, l1 = 0.0f;
    float O[8][4];
    #pragma unroll
    for (int fn = 0; fn < 8; fn++)
        #pragma unroll
        for (int r = 0; r < 4; r++)
            O[fn][r] = 0.0f;

    const int pr0 = warp * 16 + g;
    const int r0g = q0 + pr0;
    const int r1g = r0g + 8;
    const int ntiles = 2 * bx + 2;

    for (int kt = 0; kt < ntiles; kt++) {
        const int cur = kt & 1;

        cp_wait<0>();
        __syncthreads();

        if (kt + 1 < ntiles) {
            const uint32_t bufw = 4096 + (1 - cur) * 4096;
            const long rowoff = hb32 + (long)((kt + 1) * 32 + sr) * 32;
            #pragma unroll
            for (int pl = 0; pl < 2; pl++)
                #pragma unroll
                for (int j = 0; j < 2; j++) {
                    const int cc = sc + j * 4;
                    const uint32_t koff = (sr << 5) + ((cc ^ (sr & 7)) << 2);
                    cp_async16(smb + ((bufw + pl * 1024 + koff) << 2),
                               g_Kbf + (long)pl * PLSTR + rowoff + cc * 4);
                    cp_async16(smb + ((bufw + 2048 + pl * 1024 + koff) << 2),
                               g_Vbf + (long)pl * PLSTR + rowoff + cc * 4);
                }
            cp_commit();
        }

        const uint32_t kab = kab_l + ((4096 + cur * 4096) << 2);
        const uint32_t vab = kab_l + ((4096 + cur * 4096 + 2048) << 2);

        float S[4][4];
        #pragma unroll
        for (int fn = 0; fn < 4; fn++)
            #pragma unroll
            for (int r = 0; r < 4; r++)
                S[fn][r] = 0.0f;

        #pragma unroll
        for (int kc = 0; kc < 4; kc++) {
            uint32_t ah0, ah1, ah2, ah3, al0, al1, al2, al3;
            const uint32_t qoff = (uint32_t)(((2 * kc + aAc) ^ lr) << 4);
            ldsm_x4(ah0, ah1, ah2, ah3, qab + qoff);
            ldsm_x4(al0, al1, al2, al3, qab + 8192 + qoff);

            uint32_t bh0[4], bh1[4], bl0[4], bl1[4];
            const uint32_t k0off = (uint32_t)(((2 * kc)     ^ lr) << 4);
            const uint32_t k1off = (uint32_t)(((2 * kc + 1) ^ lr) << 4);
            ldsm_x4(bh0[0], bh0[1], bh0[2], bh0[3], kab + k0off);
            ldsm_x4(bh1[0], bh1[1], bh1[2], bh1[3], kab + k1off);
            ldsm_x4(bl0[0], bl0[1], bl0[2], bl0[3], kab + 4096 + k0off);
            ldsm_x4(bl1[0], bl1[1], bl1[2], bl1[3], kab + 4096 + k1off);

            #pragma unroll
            for (int fn = 0; fn < 4; fn++) {
                mma_bf16(S[fn], ah0, ah1, ah2, ah3, bh0[fn], bh1[fn]);
                mma_bf16(S[fn], ah0, ah1, ah2, ah3, bl0[fn], bl1[fn]);
                mma_bf16(S[fn], al0, al1, al2, al3, bh0[fn], bh1[fn]);
            }
        }

        const int key0 = kt * 32;
        if (kt >= 2 * bx) {
            #pragma unroll
            for (int fn = 0; fn < 4; fn++) {
                const int cg = key0 + fn * 8 + 2 * t;
                if (cg     > r0g) S[fn][0] = -1e30f;
                if (cg + 1 > r0g) S[fn][1] = -1e30f;
                if (cg     > r1g) S[fn][2] = -1e30f;
                if (cg + 1 > r1g) S[fn][3] = -1e30f;
            }
        }

        float mt0 = fmaxf(fmaxf(S[0][0], S[0][1]), fmaxf(S[1][0], S[1][1]));
        mt0 = fmaxf(mt0, fmaxf(fmaxf(S[2][0], S[2][1]), fmaxf(S[3][0], S[3][1])));
        float mt1 = fmaxf(fmaxf(S[0][2], S[0][3]), fmaxf(S[1][2], S[1][3]));
        mt1 = fmaxf(mt1, fmaxf(fmaxf(S[2][2], S[2][3]), fmaxf(S[3][2], S[3][3])));
        mt0 = fmaxf(mt0, __shfl_xor_sync(0xffffffffu, mt0, 1));
        mt0 = fmaxf(mt0, __shfl_xor_sync(0xffffffffu, mt0, 2));
        mt1 = fmaxf(mt1, __shfl_xor_sync(0xffffffffu, mt1, 1));
        mt1 = fmaxf(mt1, __shfl_xor_sync(0xffffffffu, mt1, 2));

        const float m0n = fmaxf(m0, mt0);
        const float m1n = fmaxf(m1, mt1);
        const float a0 = __expf(m0 - m0n);
        const float a1 = __expf(m1 - m1n);

        float ps0 = 0.0f, ps1 = 0.0f;
        #pragma unroll
        for (int fn = 0; fn < 4; fn++) {
            S[fn][0] = __expf(S[fn][0] - m0n);
            S[fn][1] = __expf(S[fn][1] - m0n);
            S[fn][2] = __expf(S[fn][2] - m1n);
            S[fn][3] = __expf(S[fn][3] - m1n);
            ps0 += S[fn][0] + S[fn][1];
            ps1 += S[fn][2] + S[fn][3];
        }
        ps0 += __shfl_xor_sync(0xffffffffu, ps0, 1);
        ps0 += __shfl_xor_sync(0xffffffffu, ps0, 2);
        ps1 += __shfl_xor_sync(0xffffffffu, ps1, 1);
        ps1 += __shfl_xor_sync(0xffffffffu, ps1, 2);

        l0 = l0 * a0 + ps0;
        l1 = l1 * a1 + ps1;
        m0 = m0n;
        m1 = m1n;

        #pragma unroll
        for (int fn = 0; fn < 8; fn++) {
            O[fn][0] *= a0;
            O[fn][1] *= a0;
            O[fn][2] *= a1;
            O[fn][3] *= a1;
        }

        uint32_t pah[2][4], pal[2][4];
        #pragma unroll
        for (int kc = 0; kc < 2; kc++) {
            split_bf16(S[2 * kc][0],     S[2 * kc][1],     pah[kc][0], pal[kc][0]);
            split_bf16(S[2 * kc][2],     S[2 * kc][3],     pah[kc][1], pal[kc][1]);
            split_bf16(S[2 * kc + 1][0], S[2 * kc + 1][1], pah[kc][2], pal[kc][2]);
            split_bf16(S[2 * kc + 1][2], S[2 * kc + 1][3], pah[kc][3], pal[kc][3]);
        }

        #pragma unroll
        for (int fn = 0; fn < 8; fn++) {
            uint32_t vh[4], vl[4];
            const uint32_t voff = (uint32_t)((fn ^ vfo) << 4);
            ldsm_x4_t(vh[0], vh[1], vh[2], vh[3], vab + voff);
            ldsm_x4_t(vl[0], vl[1], vl[2], vl[3], vab + 4096 + voff);
            mma_bf16(O[fn], pah[0][0], pah[0][1], pah[0][2], pah[0][3], vh[0], vh[1]);
            mma_bf16(O[fn], pah[0][0], pah[0][1], pah[0][2], pah[0][3], vl[0], vl[1]);
            mma_bf16(O[fn], pal[0][0], pal[0][1], pal[0][2], pal[0][3], vh[0], vh[1]);
            mma_bf16(O[fn], pah[1][0], pah[1][1], pah[1][2], pah[1][3], vh[2], vh[3]);
            mma_bf16(O[fn], pah[1][0], pah[1][1], pah[1][2], pah[1][3], vl[2], vl[3]);
            mma_bf16(O[fn], pal[1][0], pal[1][1], pal[1][2], pal[1][3], vh[2], vh[3]);
        }
    }

    const float il0 = 1.0f / l0;
    const float il1 = 1.0f / l1;
    const long o0 = ((long)(b * SS + r0g)) * DD + (long)h * DK;
    const long o1 = ((long)(b * SS + r1g)) * DD + (long)h * DK;
    #pragma unroll
    for (int fn = 0; fn < 8; fn++) {
        const int col = fn * 8 + 2 * t;
        *(float2*)(g_attn + o0 + col) = make_float2(O[fn][0] * il0, O[fn][1] * il0);
        *(float2*)(g_attn + o1 + col) = make_float2(O[fn][2] * il1, O[fn][3] * il1);
    }
}

// ---------------- launch ----------------
extern "C" void kernel_launch(void* const* d_in, const int* in_sizes, int n_in,
                              void* d_out, int out_size)
{
    (void)in_sizes; (void)n_in; (void)out_size;
    const float* x    = (const float*)d_in[0];
    const int*   tpos = (const int*)  d_in[1];
    const float* W_Q  = (const float*)d_in[2];
    const float* W_K  = (const float*)d_in[3];
    const float* W_V  = (const float*)d_in[4];
    const float* W_O  = (const float*)d_in[5];
    const float* cosT = (const float*)d_in[6];
    const float* sinT = (const float*)d_in[7];
    float* out = (float*)d_out;

    void *pQbf, *pKbf, *pVbf, *pAttn;
    cudaGetSymbolAddress(&pQbf, g_Qbf);
    cudaGetSymbolAddress(&pKbf, g_Kbf);
    cudaGetSymbolAddress(&pVbf, g_Vbf);
    cudaGetSymbolAddress(&pAttn, g_attn);

    static int smem_set = 0;
    if (!smem_set) {
        cudaFuncSetAttribute(gemm_tf32_kernel,
                             cudaFuncAttributeMaxDynamicSharedMemorySize,
                             GEMM_SMEM_FLOATS * sizeof(float));
        smem_set = 1;
    }

    dim3 gblk(256);
    dim3 ggrid(1024 / 128, MM / 128);   // (8, 32)
    const size_t gsmem = GEMM_SMEM_FLOATS * sizeof(float);

    gemm_tf32_kernel<<<ggrid, gblk, gsmem>>>(x, W_Q, pQbf, 1, tpos, cosT, sinT);
    gemm_tf32_kernel<<<ggrid, gblk, gsmem>>>(x, W_K, pKbf, 2, tpos, cosT, sinT);
    gemm_tf32_kernel<<<ggrid, gblk, gsmem>>>(x, W_V, pVbf, 3, tpos, cosT, sinT);

    dim3 agrid(SS / 64, BB * HH);        // (32, 32) — launch #4: profiled slot
    flash_attn_kernel<<<agrid, 128>>>();

    gemm_tf32_kernel<<<ggrid, gblk, gsmem>>>((const float*)pAttn, W_O, out, 0, tpos, cosT, sinT);
}

// round 13
// speedup vs baseline: 1.0980x; 1.0980x over previous
#include <cuda_runtime.h>
#include <cuda_bf16.h>
#include <math.h>
#include <stdint.h>
#include <string.h>

#define BB 2
#define SS 2048
#define DD 1024
#define HH 16
#define DK 64
#define MM (BB*SS)   // 4096
#define PLSTR (BB*HH*SS*32)   // words per bf16 plane (2,097,152)

// ---------------- scratch (static device memory; no allocations) ----------------
__device__ uint32_t g_Qbf[2*PLSTR];  // [pl][bh][s][32w] bf16x2, rope'd, x0.125
__device__ uint32_t g_Kbf[2*PLSTR];  // [pl][bh][s][32w] bf16x2, rope'd
__device__ uint32_t g_Vbf[2*PLSTR];  // [pl][bh][s][32w] bf16x2
__device__ float    g_attn[BB*SS*DD];

// ---------------- TF32 helpers (GEMMs) ----------------
__device__ __forceinline__ float to_tf32(float x) {
    float y;
    asm("cvt.rna.tf32.f32 %0, %1;" : "=f"(y) : "f"(x));
    return y;
}

__device__ __forceinline__ void mma_tf32(float c[4],
                                         uint32_t a0, uint32_t a1, uint32_t a2, uint32_t a3,
                                         uint32_t b0, uint32_t b1)
{
    asm volatile("mma.sync.aligned.m16n8k8.row.col.f32.tf32.tf32.f32 "
                 "{%0,%1,%2,%3}, {%4,%5,%6,%7}, {%8,%9}, {%0,%1,%2,%3};"
                 : "+f"(c[0]), "+f"(c[1]), "+f"(c[2]), "+f"(c[3])
                 : "r"(a0), "r"(a1), "r"(a2), "r"(a3), "r"(b0), "r"(b1));
}

// ---------------- BF16 helpers (attention) ----------------
__device__ __forceinline__ void mma_bf16(float c[4],
                                         uint32_t a0, uint32_t a1, uint32_t a2, uint32_t a3,
                                         uint32_t b0, uint32_t b1)
{
    asm volatile("mma.sync.aligned.m16n8k16.row.col.f32.bf16.bf16.f32 "
                 "{%0,%1,%2,%3}, {%4,%5,%6,%7}, {%8,%9}, {%0,%1,%2,%3};"
                 : "+f"(c[0]), "+f"(c[1]), "+f"(c[2]), "+f"(c[3])
                 : "r"(a0), "r"(a1), "r"(a2), "r"(a3), "r"(b0), "r"(b1));
}

__device__ __forceinline__ void ldsm_x4(uint32_t& r0, uint32_t& r1,
                                        uint32_t& r2, uint32_t& r3, uint32_t addr)
{
    asm volatile("ldmatrix.sync.aligned.m8n8.x4.shared.b16 {%0,%1,%2,%3}, [%4];"
                 : "=r"(r0), "=r"(r1), "=r"(r2), "=r"(r3) : "r"(addr));
}

__device__ __forceinline__ void ldsm_x4_t(uint32_t& r0, uint32_t& r1,
                                          uint32_t& r2, uint32_t& r3, uint32_t addr)
{
    asm volatile("ldmatrix.sync.aligned.m8n8.x4.trans.shared.b16 {%0,%1,%2,%3}, [%4];"
                 : "=r"(r0), "=r"(r1), "=r"(r2), "=r"(r3) : "r"(addr));
}

__device__ __forceinline__ void cp_async16(uint32_t saddr, const void* gptr) {
    asm volatile("cp.async.cg.shared.global [%0], [%1], 16;"
                 :: "r"(saddr), "l"(gptr));
}
__device__ __forceinline__ void cp_commit() {
    asm volatile("cp.async.commit_group;");
}
template<int N>
__device__ __forceinline__ void cp_wait() {
    asm volatile("cp.async.wait_group %0;" :: "n"(N));
}

// hi = bf16x2(x,y), lo = bf16x2(x-hi.x, y-hi.y)
__device__ __forceinline__ void split_bf16(float x, float y, uint32_t& hi, uint32_t& lo)
{
    __nv_bfloat162 h = __floats2bfloat162_rn(x, y);
    float hx = __bfloat162float(h.x);
    float hy = __bfloat162float(h.y);
    __nv_bfloat162 l = __floats2bfloat162_rn(x - hx, y - hy);
    hi = *reinterpret_cast<uint32_t*>(&h);
    lo = *reinterpret_cast<uint32_t*>(&l);
}

// ---------------- TF32 GEMM core (R10 schedule: sync loads, cvt at staging) ----------------
#define AS_STRIDE 20
#define BS_STRIDE 136

__device__ __forceinline__ void gemm_core(const float* __restrict__ A,
                                          const float* __restrict__ W,
                                          float* As, float* Bs,
                                          float acc[4][4][4])
{
    const int K = 1024, N = 1024;
    const int tid  = threadIdx.x;
    const int warp = tid >> 5;
    const int lane = tid & 31;
    const int g = lane >> 2;
    const int t = lane & 3;

    const int warp_m = (warp & 1) * 64;
    const int warp_n = (warp >> 1) * 32;

    const int row0 = blockIdx.y * 128;
    const int col0 = blockIdx.x * 128;

    const int a_row = tid >> 1;
    const int a_cg  = (tid & 1) * 8;
    const int b_row = tid >> 4;
    const int b_col = (tid & 15) * 8;

    for (int k0 = 0; k0 < K; k0 += 16) {
        {
            const float4* src = (const float4*)&A[(long)(row0 + a_row) * K + k0 + a_cg];
            float4 v0 = src[0];
            float4 v1 = src[1];
            float4 w0 = make_float4(to_tf32(v0.x), to_tf32(v0.y), to_tf32(v0.z), to_tf32(v0.w));
            float4 w1 = make_float4(to_tf32(v1.x), to_tf32(v1.y), to_tf32(v1.z), to_tf32(v1.w));
            float4* dst = (float4*)&As[a_row * AS_STRIDE + a_cg];
            dst[0] = w0;
            dst[1] = w1;
        }
        {
            const float4* src = (const float4*)&W[(long)(k0 + b_row) * N + col0 + b_col];
            float4 v0 = src[0];
            float4 v1 = src[1];
            float4 w0 = make_float4(to_tf32(v0.x), to_tf32(v0.y), to_tf32(v0.z), to_tf32(v0.w));
            float4 w1 = make_float4(to_tf32(v1.x), to_tf32(v1.y), to_tf32(v1.z), to_tf32(v1.w));
            float4* dst = (float4*)&Bs[b_row * BS_STRIDE + b_col];
            dst[0] = w0;
            dst[1] = w1;
        }
        __syncthreads();

        #pragma unroll
        for (int chunk = 0; chunk < 2; chunk++) {
            const int kc = chunk * 8;

            uint32_t af[4][4];
            #pragma unroll
            for (int fm = 0; fm < 4; fm++) {
                const float* pa = &As[(warp_m + fm * 16 + g) * AS_STRIDE + kc + t];
                af[fm][0] = __float_as_uint(pa[0]);
                af[fm][1] = __float_as_uint(pa[8 * AS_STRIDE]);
                af[fm][2] = __float_as_uint(pa[4]);
                af[fm][3] = __float_as_uint(pa[8 * AS_STRIDE + 4]);
            }
            uint32_t bf[4][2];
            #pragma unroll
            for (int fn = 0; fn < 4; fn++) {
                const float* pb = &Bs[(kc + t) * BS_STRIDE + warp_n + fn * 8 + g];
                bf[fn][0] = __float_as_uint(pb[0]);
                bf[fn][1] = __float_as_uint(pb[4 * BS_STRIDE]);
            }

            #pragma unroll
            for (int fm = 0; fm < 4; fm++)
                #pragma unroll
                for (int fn = 0; fn < 4; fn++)
                    mma_tf32(acc[fm][fn],
                             af[fm][0], af[fm][1], af[fm][2], af[fm][3],
                             bf[fn][0], bf[fn][1]);
        }
        __syncthreads();
    }
}

// fused QKV projection: gridDim.z = 3 selects Q/K/V
__global__ void __launch_bounds__(256, 2)
gemm_qkv_kernel(const float* __restrict__ A,
                const float* __restrict__ W_Q,
                const float* __restrict__ W_K,
                const float* __restrict__ W_V,
                uint32_t* __restrict__ Qb,
                uint32_t* __restrict__ Kb,
                uint32_t* __restrict__ Vb,
                const int* __restrict__ tpos,
                const float* __restrict__ cosT,
                const float* __restrict__ sinT)
{
    __shared__ float As[128 * AS_STRIDE];
    __shared__ float Bs[16 * BS_STRIDE];

    const int z = blockIdx.z;                 // 0=Q, 1=K, 2=V
    const float* W = (z == 0) ? W_Q : (z == 1) ? W_K : W_V;
    uint32_t* Cb   = (z == 0) ? Qb  : (z == 1) ? Kb  : Vb;

    float acc[4][4][4];
    #pragma unroll
    for (int i = 0; i < 4; i++)
        #pragma unroll
        for (int j = 0; j < 4; j++)
            #pragma unroll
            for (int r = 0; r < 4; r++)
                acc[i][j][r] = 0.0f;

    gemm_core(A, W, As, Bs, acc);

    // epilogue: rope (Q,K), scale (Q), bf16 split planes, [B,H,S,32w] layout
    const int tid  = threadIdx.x;
    const int warp = tid >> 5;
    const int lane = tid & 31;
    const int g = lane >> 2;
    const int t = lane & 3;
    const int warp_m = (warp & 1) * 64;
    const int warp_n = (warp >> 1) * 32;
    const int row0 = blockIdx.y * 128;
    const int col0 = blockIdx.x * 128;

    #pragma unroll
    for (int fm = 0; fm < 4; fm++) {
        const int m0r = row0 + warp_m + fm * 16 + g;
        const int bb = m0r >> 11;
        const int s0 = m0r & 2047;
        const int s1 = s0 + 8;
        int p0 = 0, p1 = 0;
        if (z != 2) { p0 = tpos[s0]; p1 = tpos[s1]; }
        #pragma unroll
        for (int fn = 0; fn < 4; fn++) {
            const int c0 = col0 + warp_n + fn * 8 + 2 * t;
            const int hh = c0 >> 6;
            const int d  = c0 & 63;
            const int pi = d >> 1;
            float x0 = acc[fm][fn][0], y0 = acc[fm][fn][1];
            float x1 = acc[fm][fn][2], y1 = acc[fm][fn][3];
            if (z != 2) {
                float cc = cosT[p0 * 32 + pi], ssn = sinT[p0 * 32 + pi];
                float xe = cc * x0 - ssn * y0;
                float xo = ssn * x0 + cc * y0;
                x0 = xe; y0 = xo;
                cc = cosT[p1 * 32 + pi]; ssn = sinT[p1 * 32 + pi];
                xe = cc * x1 - ssn * y1;
                xo = ssn * x1 + cc * y1;
                x1 = xe; y1 = xo;
            }
            if (z == 0) {
                x0 *= 0.125f; y0 *= 0.125f;
                x1 *= 0.125f; y1 *= 0.125f;
            }
            uint32_t hi0, lo0, hi1, lo1;
            split_bf16(x0, y0, hi0, lo0);
            split_bf16(x1, y1, hi1, lo1);
            const long i0 = ((long)(bb * HH + hh) * SS + s0) * 32 + pi;
            const long i1 = ((long)(bb * HH + hh) * SS + s1) * 32 + pi;
            Cb[i0]         = hi0;
            Cb[PLSTR + i0] = lo0;
            Cb[i1]         = hi1;
            Cb[PLSTR + i1] = lo1;
        }
    }
}

// output projection: plain fp32 write
__global__ void __launch_bounds__(256, 2)
gemm_out_kernel(const float* __restrict__ A, const float* __restrict__ W,
                float* __restrict__ C)
{
    __shared__ float As[128 * AS_STRIDE];
    __shared__ float Bs[16 * BS_STRIDE];

    float acc[4][4][4];
    #pragma unroll
    for (int i = 0; i < 4; i++)
        #pragma unroll
        for (int j = 0; j < 4; j++)
            #pragma unroll
            for (int r = 0; r < 4; r++)
                acc[i][j][r] = 0.0f;

    gemm_core(A, W, As, Bs, acc);

    const int tid  = threadIdx.x;
    const int warp = tid >> 5;
    const int lane = tid & 31;
    const int g = lane >> 2;
    const int t = lane & 3;
    const int warp_m = (warp & 1) * 64;
    const int warp_n = (warp >> 1) * 32;
    const int row0 = blockIdx.y * 128;
    const int col0 = blockIdx.x * 128;

    #pragma unroll
    for (int fm = 0; fm < 4; fm++) {
        #pragma unroll
        for (int fn = 0; fn < 4; fn++) {
            int r0 = row0 + warp_m + fm * 16 + g;
            int c0 = col0 + warp_n + fn * 8 + 2 * t;
            *(float2*)&C[(long)r0 * 1024 + c0] =
                make_float2(acc[fm][fn][0], acc[fm][fn][1]);
            *(float2*)&C[(long)(r0 + 8) * 1024 + c0] =
                make_float2(acc[fm][fn][2], acc[fm][fn][3]);
        }
    }
}

// ---------------- flash attention (R10, unchanged) ----------------
__global__ void __launch_bounds__(128, 4)
flash_attn_kernel()
{
    __shared__ uint32_t smw[12288];   // 48 KB

    const int tid  = threadIdx.x;
    const int warp = tid >> 5;
    const int lane = tid & 31;
    const int g = lane >> 2;
    const int t = lane & 3;

    const int bx = gridDim.x - 1 - blockIdx.x;   // heavy tiles first
    const int bh = blockIdx.y;
    const int b = bh >> 4, h = bh & 15;
    const long hb32 = (long)bh * SS * 32;
    const int q0 = bx * 64;

    const uint32_t smb = (uint32_t)__cvta_generic_to_shared(smw);

    const int sr = tid >> 2;
    const int sc = tid & 3;
    const int qr = tid >> 1;
    const int qc = (tid & 1) * 4;

    {
        #pragma unroll
        for (int pl = 0; pl < 2; pl++)
            #pragma unroll
            for (int j = 0; j < 4; j++) {
                const int cc = qc + j;
                cp_async16(smb + ((pl * 2048 + (qr << 5) + ((cc ^ (qr & 7)) << 2)) << 2),
                           g_Qbf + (long)pl * PLSTR + hb32 + (long)(q0 + qr) * 32 + cc * 4);
            }
        #pragma unroll
        for (int pl = 0; pl < 2; pl++)
            #pragma unroll
            for (int j = 0; j < 2; j++) {
                const int cc = sc + j * 4;
                const uint32_t koff = (sr << 5) + ((cc ^ (sr & 7)) << 2);
                cp_async16(smb + ((4096 + pl * 1024 + koff) << 2),
                           g_Kbf + (long)pl * PLSTR + hb32 + (long)sr * 32 + cc * 4);
                cp_async16(smb + ((4096 + 2048 + pl * 1024 + koff) << 2),
                           g_Vbf + (long)pl * PLSTR + hb32 + (long)sr * 32 + cc * 4);
            }
        cp_commit();
    }

    const int lr  = lane & 7;
    const int sel = lane >> 3;
    const uint32_t qab = smb + (uint32_t)(warp * 16 + lr + 8 * (sel & 1)) * 128;
    const int aAc = sel >> 1;
    const uint32_t kab_l = smb + (uint32_t)lane * 128;
    const int vfo = lr;

    float m0 = -1e30f, m1 = -1e30f, l0 = 0.0f, l1 = 0.0f;
    float O[8][4];
    #pragma unroll
    for (int fn = 0; fn < 8; fn++)
        #pragma unroll
        for (int r = 0; r < 4; r++)
            O[fn][r] = 0.0f;

    const int pr0 = warp * 16 + g;
    const int r0g = q0 + pr0;
    const int r1g = r0g + 8;
    const int ntiles = 2 * bx + 2;

    for (int kt = 0; kt < ntiles; kt++) {
        const int cur = kt & 1;

        cp_wait<0>();
        __syncthreads();

        if (kt + 1 < ntiles) {
            const uint32_t bufw = 4096 + (1 - cur) * 4096;
            const long rowoff = hb32 + (long)((kt + 1) * 32 + sr) * 32;
            #pragma unroll
            for (int pl = 0; pl < 2; pl++)
                #pragma unroll
                for (int j = 0; j < 2; j++) {
                    const int cc = sc + j * 4;
                    const uint32_t koff = (sr << 5) + ((cc ^ (sr & 7)) << 2);
                    cp_async16(smb + ((bufw + pl * 1024 + koff) << 2),
                               g_Kbf + (long)pl * PLSTR + rowoff + cc * 4);
                    cp_async16(smb + ((bufw + 2048 + pl * 1024 + koff) << 2),
                               g_Vbf + (long)pl * PLSTR + rowoff + cc * 4);
                }
            cp_commit();
        }

        const uint32_t kab = kab_l + ((4096 + cur * 4096) << 2);
        const uint32_t vab = kab_l + ((4096 + cur * 4096 + 2048) << 2);

        float S[4][4];
        #pragma unroll
        for (int fn = 0; fn < 4; fn++)
            #pragma unroll
            for (int r = 0; r < 4; r++)
                S[fn][r] = 0.0f;

        #pragma unroll
        for (int kc = 0; kc < 4; kc++) {
            uint32_t ah0, ah1, ah2, ah3, al0, al1, al2, al3;
            const uint32_t qoff = (uint32_t)(((2 * kc + aAc) ^ lr) << 4);
            ldsm_x4(ah0, ah1, ah2, ah3, qab + qoff);
            ldsm_x4(al0, al1, al2, al3, qab + 8192 + qoff);

            uint32_t bh0[4], bh1[4], bl0[4], bl1[4];
            const uint32_t k0off = (uint32_t)(((2 * kc)     ^ lr) << 4);
            const uint32_t k1off = (uint32_t)(((2 * kc + 1) ^ lr) << 4);
            ldsm_x4(bh0[0], bh0[1], bh0[2], bh0[3], kab + k0off);
            ldsm_x4(bh1[0], bh1[1], bh1[2], bh1[3], kab + k1off);
            ldsm_x4(bl0[0], bl0[1], bl0[2], bl0[3], kab + 4096 + k0off);
            ldsm_x4(bl1[0], bl1[1], bl1[2], bl1[3], kab + 4096 + k1off);

            #pragma unroll
            for (int fn = 0; fn < 4; fn++) {
                mma_bf16(S[fn], ah0, ah1, ah2, ah3, bh0[fn], bh1[fn]);
                mma_bf16(S[fn], ah0, ah1, ah2, ah3, bl0[fn], bl1[fn]);
                mma_bf16(S[fn], al0, al1, al2, al3, bh0[fn], bh1[fn]);
            }
        }

        const int key0 = kt * 32;
        if (kt >= 2 * bx) {
            #pragma unroll
            for (int fn = 0; fn < 4; fn++) {
                const int cg = key0 + fn * 8 + 2 * t;
                if (cg     > r0g) S[fn][0] = -1e30f;
                if (cg + 1 > r0g) S[fn][1] = -1e30f;
                if (cg     > r1g) S[fn][2] = -1e30f;
                if (cg + 1 > r1g) S[fn][3] = -1e30f;
            }
        }

        float mt0 = fmaxf(fmaxf(S[0][0], S[0][1]), fmaxf(S[1][0], S[1][1]));
        mt0 = fmaxf(mt0, fmaxf(fmaxf(S[2][0], S[2][1]), fmaxf(S[3][0], S[3][1])));
        float mt1 = fmaxf(fmaxf(S[0][2], S[0][3]), fmaxf(S[1][2], S[1][3]));
        mt1 = fmaxf(mt1, fmaxf(fmaxf(S[2][2], S[2][3]), fmaxf(S[3][2], S[3][3])));
        mt0 = fmaxf(mt0, __shfl_xor_sync(0xffffffffu, mt0, 1));
        mt0 = fmaxf(mt0, __shfl_xor_sync(0xffffffffu, mt0, 2));
        mt1 = fmaxf(mt1, __shfl_xor_sync(0xffffffffu, mt1, 1));
        mt1 = fmaxf(mt1, __shfl_xor_sync(0xffffffffu, mt1, 2));

        const float m0n = fmaxf(m0, mt0);
        const float m1n = fmaxf(m1, mt1);
        const float a0 = __expf(m0 - m0n);
        const float a1 = __expf(m1 - m1n);

        float ps0 = 0.0f, ps1 = 0.0f;
        #pragma unroll
        for (int fn = 0; fn < 4; fn++) {
            S[fn][0] = __expf(S[fn][0] - m0n);
            S[fn][1] = __expf(S[fn][1] - m0n);
            S[fn][2] = __expf(S[fn][2] - m1n);
            S[fn][3] = __expf(S[fn][3] - m1n);
            ps0 += S[fn][0] + S[fn][1];
            ps1 += S[fn][2] + S[fn][3];
        }
        ps0 += __shfl_xor_sync(0xffffffffu, ps0, 1);
        ps0 += __shfl_xor_sync(0xffffffffu, ps0, 2);
        ps1 += __shfl_xor_sync(0xffffffffu, ps1, 1);
        ps1 += __shfl_xor_sync(0xffffffffu, ps1, 2);

        l0 = l0 * a0 + ps0;
        l1 = l1 * a1 + ps1;
        m0 = m0n;
        m1 = m1n;

        #pragma unroll
        for (int fn = 0; fn < 8; fn++) {
            O[fn][0] *= a0;
            O[fn][1] *= a0;
            O[fn][2] *= a1;
            O[fn][3] *= a1;
        }

        uint32_t pah[2][4], pal[2][4];
        #pragma unroll
        for (int kc = 0; kc < 2; kc++) {
            split_bf16(S[2 * kc][0],     S[2 * kc][1],     pah[kc][0], pal[kc][0]);
            split_bf16(S[2 * kc][2],     S[2 * kc][3],     pah[kc][1], pal[kc][1]);
            split_bf16(S[2 * kc + 1][0], S[2 * kc + 1][1], pah[kc][2], pal[kc][2]);
            split_bf16(S[2 * kc + 1][2], S[2 * kc + 1][3], pah[kc][3], pal[kc][3]);
        }

        #pragma unroll
        for (int fn = 0; fn < 8; fn++) {
            uint32_t vh[4], vl[4];
            const uint32_t voff = (uint32_t)((fn ^ vfo) << 4);
            ldsm_x4_t(vh[0], vh[1], vh[2], vh[3], vab + voff);
            ldsm_x4_t(vl[0], vl[1], vl[2], vl[3], vab + 4096 + voff);
            mma_bf16(O[fn], pah[0][0], pah[0][1], pah[0][2], pah[0][3], vh[0], vh[1]);
            mma_bf16(O[fn], pah[0][0], pah[0][1], pah[0][2], pah[0][3], vl[0], vl[1]);
            mma_bf16(O[fn], pal[0][0], pal[0][1], pal[0][2], pal[0][3], vh[0], vh[1]);
            mma_bf16(O[fn], pah[1][0], pah[1][1], pah[1][2], pah[1][3], vh[2], vh[3]);
            mma_bf16(O[fn], pah[1][0], pah[1][1], pah[1][2], pah[1][3], vl[2], vl[3]);
            mma_bf16(O[fn], pal[1][0], pal[1][1], pal[1][2], pal[1][3], vh[2], vh[3]);
        }
    }

    const float il0 = 1.0f / l0;
    const float il1 = 1.0f / l1;
    const long o0 = ((long)(b * SS + r0g)) * DD + (long)h * DK;
    const long o1 = ((long)(b * SS + r1g)) * DD + (long)h * DK;
    #pragma unroll
    for (int fn = 0; fn < 8; fn++) {
        const int col = fn * 8 + 2 * t;
        *(float2*)(g_attn + o0 + col) = make_float2(O[fn][0] * il0, O[fn][1] * il0);
        *(float2*)(g_attn + o1 + col) = make_float2(O[fn][2] * il1, O[fn][3] * il1);
    }
}

// ---------------- launch ----------------
extern "C" void kernel_launch(void* const* d_in, const int* in_sizes, int n_in,
                              void* d_out, int out_size)
{
    (void)in_sizes; (void)n_in; (void)out_size;
    const float* x    = (const float*)d_in[0];
    const int*   tpos = (const int*)  d_in[1];
    const float* W_Q  = (const float*)d_in[2];
    const float* W_K  = (const float*)d_in[3];
    const float* W_V  = (const float*)d_in[4];
    const float* W_O  = (const float*)d_in[5];
    const float* cosT = (const float*)d_in[6];
    const float* sinT = (const float*)d_in[7];
    float* out = (float*)d_out;

    void *pQbf, *pKbf, *pVbf, *pAttn;
    cudaGetSymbolAddress(&pQbf, g_Qbf);
    cudaGetSymbolAddress(&pKbf, g_Kbf);
    cudaGetSymbolAddress(&pVbf, g_Vbf);
    cudaGetSymbolAddress(&pAttn, g_attn);

    dim3 gblk(256);
    dim3 qkvgrid(1024 / 128, MM / 128, 3);   // (8, 32, 3) — fused QKV
    dim3 ogrid(1024 / 128, MM / 128);        // (8, 32)

    gemm_qkv_kernel<<<qkvgrid, gblk>>>(x, W_Q, W_K, W_V,
                                       (uint32_t*)pQbf, (uint32_t*)pKbf, (uint32_t*)pVbf,
                                       tpos, cosT, sinT);

    dim3 agrid(SS / 64, BB * HH);            // (32, 32)
    flash_attn_kernel<<<agrid, 128>>>();

    gemm_out_kernel<<<ogrid, gblk>>>((const float*)pAttn, W_O, out);
}